// round 13
// baseline (speedup 1.0000x reference)
#include <cuda_runtime.h>
#include <cuda_bf16.h>
#include <mma.h>
#include <cstdint>
#include <math.h>

using namespace nvcuda;

// Problem constants
#define NB    4
#define NTOK  4096          // H*W
#define NC    1024          // C
#define NH    8             // heads
#define HC    128           // channels per head
#define NO    2048          // 2C
#define NCHUNK 32           // token chunks for S kernel (4096/128)

// ---------------- scratch (static device allocations only) ----------------
__device__ float g_qmax [NB * NTOK * NH];
__device__ float g_qfs  [NB * NTOK * NH];
__device__ float g_g    [NB * NC];
__device__ float g_Spart[(size_t)NB * NH * NCHUNK * HC * HC];   // 64 MB
__device__ float g_S    [NB * NH * HC * HC];                    // 2 MB
__device__ __nv_bfloat16 g_x1h[(size_t)NB * NTOK * NC];         // 32 MB
__device__ __nv_bfloat16 g_x1l[(size_t)NB * NTOK * NC];         // 32 MB
__device__ __nv_bfloat16 g_W2h[(size_t)NB * NO * NC];           // 16 MB
__device__ __nv_bfloat16 g_W2l[(size_t)NB * NO * NC];           // 16 MB

// packed f32x2 helpers (compiled clean in Round 10)
#define FMA_F32X2(acc, ap, bp) \
    asm("fma.rn.f32x2 %0, %1, %2, %0;" : "+l"(acc) : "l"(ap), "l"(bp))
#define BCAST_F32X2(out, f) \
    asm("mov.b64 %0, {%1, %1};" : "=l"(out) : "f"(f))
#define UNPACK_F32X2(lo, hi, in) \
    asm("mov.b64 {%0, %1}, %2;" : "=f"(lo), "=f"(hi) : "l"(in))

// ---------------- kernel 1: per-token (query) softmax stats ----------------
__global__ void qstats_kernel(const float* __restrict__ x2) {
    const int bn   = blockIdx.x;
    const int w    = threadIdx.x >> 5;
    const int lane = threadIdx.x & 31;
    const float4 v = *(const float4*)(x2 + (size_t)bn * NC + w * HC + lane * 4);
    float m = fmaxf(fmaxf(v.x, v.y), fmaxf(v.z, v.w));
    #pragma unroll
    for (int off = 16; off; off >>= 1) m = fmaxf(m, __shfl_xor_sync(0xffffffffu, m, off));
    float s = __expf(v.x - m) + __expf(v.y - m) + __expf(v.z - m) + __expf(v.w - m);
    #pragma unroll
    for (int off = 16; off; off >>= 1) s += __shfl_xor_sync(0xffffffffu, s, off);
    if (lane == 0) {
        g_qmax[bn * NH + w] = m;
        g_qfs [bn * NH + w] = sqrtf(__expf(m) / s);
    }
}

// ---------------- kernel 2: per-column (key) softmax stats ----------------
__global__ void kstats_kernel(const float* __restrict__ x2) {
    const int b   = blockIdx.y;
    const int ch0 = blockIdx.x * 64;
    const int t   = threadIdx.x;
    const int q   = t & 15;
    const int ro  = t >> 4;
    const float* base = x2 + (size_t)b * NTOK * NC + ch0 + q * 4;
    float m[4] = {-1e30f, -1e30f, -1e30f, -1e30f};
    float s[4] = {0.f, 0.f, 0.f, 0.f};
    for (int it = 0; it < NTOK / 16; ++it) {
        float4 v = *(const float4*)(base + (size_t)(it * 16 + ro) * NC);
        float vv[4] = {v.x, v.y, v.z, v.w};
        #pragma unroll
        for (int k = 0; k < 4; k++) {
            float x = vv[k];
            if (x > m[k]) { s[k] = s[k] * __expf(m[k] - x) + 1.0f; m[k] = x; }
            else          { s[k] += __expf(x - m[k]); }
        }
    }
    __shared__ float sm[16][64];
    __shared__ float ss[16][64];
    #pragma unroll
    for (int k = 0; k < 4; k++) { sm[ro][q * 4 + k] = m[k]; ss[ro][q * 4 + k] = s[k]; }
    __syncthreads();
    if (t < 64) {
        float M = -1e30f;
        #pragma unroll
        for (int r = 0; r < 16; r++) M = fmaxf(M, sm[r][t]);
        float S = 0.f;
        #pragma unroll
        for (int r = 0; r < 16; r++) S += ss[r][t] * __expf(sm[r][t] - M);
        g_g[b * NC + ch0 + t] = __expf(-M) / S;
    }
}

// ---------------- kernel 3: S partials (f32x2 FFMA2 inner loop) ----------------
__global__ void __launch_bounds__(256) s_kernel(const float* __restrict__ x2) {
    extern __shared__ float Es[];                 // [128][132]
    const int b = blockIdx.z, h = blockIdx.y, chunk = blockIdx.x;
    const int n0 = chunk * 128;
    const int t = threadIdx.x;
    {
        const int r  = t >> 1;
        const int c0 = (t & 1) * 64;
        const int n  = n0 + r;
        const float qm = g_qmax[(b * NTOK + n) * NH + h];
        const float qf = g_qfs [(b * NTOK + n) * NH + h];
        const float4* src = (const float4*)(x2 + (size_t)(b * NTOK + n) * NC + h * HC + c0);
        float* dst = Es + r * 132 + c0;
        #pragma unroll
        for (int k = 0; k < 16; k++) {
            float4 v = src[k];
            v.x = __expf(v.x - qm) * qf;
            v.y = __expf(v.y - qm) * qf;
            v.z = __expf(v.z - qm) * qf;
            v.w = __expf(v.w - qm) * qf;
            *(float4*)(dst + k * 4) = v;
        }
    }
    __syncthreads();
    const int tx = t & 15, ty = t >> 4;
    unsigned long long acc2[8][4];
    #pragma unroll
    for (int i = 0; i < 8; i++)
        #pragma unroll
        for (int j = 0; j < 4; j++) acc2[i][j] = 0ull;

    for (int n = 0; n < 128; n++) {
        const float* row = Es + n * 132;
        const float4 A0 = *(const float4*)(row + ty * 4);
        const float4 A1 = *(const float4*)(row + 64 + ty * 4);
        const ulonglong2 B0 = *(const ulonglong2*)(row + tx * 4);
        const ulonglong2 B1 = *(const ulonglong2*)(row + 64 + tx * 4);
        const unsigned long long bp[4] = {B0.x, B0.y, B1.x, B1.y};
        const float a[8] = {A0.x, A0.y, A0.z, A0.w, A1.x, A1.y, A1.z, A1.w};
        #pragma unroll
        for (int i = 0; i < 8; i++) {
            unsigned long long ap;
            BCAST_F32X2(ap, a[i]);
            #pragma unroll
            for (int j = 0; j < 4; j++) FMA_F32X2(acc2[i][j], ap, bp[j]);
        }
    }
    float gv[8];
    #pragma unroll
    for (int j = 0; j < 8; j++) {
        const int jg = (j < 4) ? (tx * 4 + j) : (64 + tx * 4 + (j - 4));
        gv[j] = g_g[b * NC + h * HC + jg];
    }
    float* Sout = g_Spart + (((size_t)(b * NH + h) * NCHUNK + chunk) * HC) * HC;
    #pragma unroll
    for (int i = 0; i < 8; i++) {
        float c[8];
        #pragma unroll
        for (int j = 0; j < 4; j++) UNPACK_F32X2(c[j * 2], c[j * 2 + 1], acc2[i][j]);
        const int ig = (i < 4) ? (ty * 4 + i) : (64 + ty * 4 + (i - 4));
        float* drow = Sout + ig * HC;
        *(float4*)(drow + tx * 4) =
            make_float4(c[0] * gv[0], c[1] * gv[1], c[2] * gv[2], c[3] * gv[3]);
        *(float4*)(drow + 64 + tx * 4) =
            make_float4(c[4] * gv[4], c[5] * gv[5], c[6] * gv[6], c[7] * gv[7]);
    }
}

// ---------------- kernel 4: reduce S partials ----------------
__global__ void s_reduce_kernel() {
    const int bh_i = blockIdx.x;
    const int j    = threadIdx.x;
    const int bh   = bh_i >> 7;
    const int i    = bh_i & 127;
    float s = 0.f;
    #pragma unroll 4
    for (int c = 0; c < NCHUNK; c++)
        s += g_Spart[(((size_t)bh * NCHUNK + c) * HC + i) * HC + j];
    g_S[((size_t)bh * HC + i) * HC + j] = s;
}

// ---------------- kernel 5: fold S into weights, emit bf16 hi/lo (f32x2 inner) ----------------
__global__ void __launch_bounds__(256) w2_kernel(const float* __restrict__ w_proj) {
    extern __shared__ float smemf[];
    float* Ssh = smemf;                    // [128][132]
    float* WT  = smemf + 128 * 132;        // [128][132]
    const int b = blockIdx.z, h = blockIdx.y, o0 = blockIdx.x * 128;
    const int t = threadIdx.x;
    {
        const int i = t >> 1, j0 = (t & 1) * 64;
        const float4* src = (const float4*)(g_S + ((size_t)(b * NH + h) * HC + i) * HC + j0);
        float4* dst = (float4*)(Ssh + i * 132 + j0);
        #pragma unroll
        for (int k = 0; k < 16; k++) dst[k] = src[k];
    }
    {
        const int o = t >> 1, i0 = (t & 1) * 64;
        const float4* src = (const float4*)(w_proj + (size_t)(o0 + o) * NC + h * HC + i0);
        #pragma unroll
        for (int k = 0; k < 16; k++) {
            float4 v = src[k];
            const int i = i0 + k * 4;
            WT[(i + 0) * 132 + o] = v.x;
            WT[(i + 1) * 132 + o] = v.y;
            WT[(i + 2) * 132 + o] = v.z;
            WT[(i + 3) * 132 + o] = v.w;
        }
    }
    __syncthreads();
    const int tx = t & 15, ty = t >> 4;
    unsigned long long acc2[8][4];
    #pragma unroll
    for (int i = 0; i < 8; i++)
        #pragma unroll
        for (int j = 0; j < 4; j++) acc2[i][j] = 0ull;

    for (int i = 0; i < 128; i++) {
        const float* wrow = WT  + i * 132;
        const float* srow = Ssh + i * 132;
        const float4 A0 = *(const float4*)(wrow + ty * 4);
        const float4 A1 = *(const float4*)(wrow + 64 + ty * 4);
        const ulonglong2 B0 = *(const ulonglong2*)(srow + tx * 4);
        const ulonglong2 B1 = *(const ulonglong2*)(srow + 64 + tx * 4);
        const unsigned long long bp[4] = {B0.x, B0.y, B1.x, B1.y};
        const float a[8] = {A0.x, A0.y, A0.z, A0.w, A1.x, A1.y, A1.z, A1.w};
        #pragma unroll
        for (int ii = 0; ii < 8; ii++) {
            unsigned long long ap;
            BCAST_F32X2(ap, a[ii]);
            #pragma unroll
            for (int jj = 0; jj < 4; jj++) FMA_F32X2(acc2[ii][jj], ap, bp[jj]);
        }
    }
    #pragma unroll
    for (int i = 0; i < 8; i++) {
        float c[8];
        #pragma unroll
        for (int j = 0; j < 4; j++) UNPACK_F32X2(c[j * 2], c[j * 2 + 1], acc2[i][j]);
        const int og = o0 + ((i < 4) ? (ty * 4 + i) : (64 + ty * 4 + (i - 4)));
        const size_t base = ((size_t)b * NO + og) * NC + h * HC;
        #pragma unroll
        for (int j = 0; j < 8; j++) {
            const int jg = (j < 4) ? (tx * 4 + j) : (64 + tx * 4 + (j - 4));
            float v = c[j];
            __nv_bfloat16 hi = __float2bfloat16_rn(v);
            __nv_bfloat16 lo = __float2bfloat16_rn(v - __bfloat162float(hi));
            g_W2h[base + jg] = hi;
            g_W2l[base + jg] = lo;
        }
    }
}

// ---------------- kernel 5b: x1 -> bf16 hi/lo ----------------
__global__ void cvt_x1_kernel(const float* __restrict__ x1) {
    const size_t i = ((size_t)blockIdx.x * 256 + threadIdx.x) * 4;
    const float4 v = *(const float4*)(x1 + i);
    float vv[4] = {v.x, v.y, v.z, v.w};
    __nv_bfloat16 h[4], l[4];
    #pragma unroll
    for (int k = 0; k < 4; k++) {
        h[k] = __float2bfloat16_rn(vv[k]);
        l[k] = __float2bfloat16_rn(vv[k] - __bfloat162float(h[k]));
    }
    ((__nv_bfloat162*)(g_x1h + i))[0] = __nv_bfloat162(h[0], h[1]);
    ((__nv_bfloat162*)(g_x1h + i))[1] = __nv_bfloat162(h[2], h[3]);
    ((__nv_bfloat162*)(g_x1l + i))[0] = __nv_bfloat162(l[0], l[1]);
    ((__nv_bfloat162*)(g_x1l + i))[1] = __nv_bfloat162(l[2], l[3]);
}

// ---------------- kernel 6: WMMA split-bf16 projection GEMM ----------------
// out[b, n0+r, o0+c] = sum_k x1[b,n0+r,k] * W2[b,o0+c,k]     (bias folded into LN)
// CTA tile 128x128, 8 warps in 2(n) x 4(o); warp tile 64x32; K chunked by 32.
// Split products: hi*hi + hi*lo + lo*hi (lo*lo dropped, ~2^-16 rel).
__global__ void __launch_bounds__(256, 2) mm_kernel(float* __restrict__ out) {
    __shared__ __nv_bfloat16 sAh[128][32];
    __shared__ __nv_bfloat16 sAl[128][32];
    __shared__ __nv_bfloat16 sBh[128][32];
    __shared__ __nv_bfloat16 sBl[128][32];

    const int b  = blockIdx.z;
    const int n0 = blockIdx.y * 128;
    const int o0 = blockIdx.x * 128;
    const int tid = threadIdx.x;
    const int wid = tid >> 5;
    const int wn = (wid & 1) * 64;      // warp row offset (n)
    const int wo = (wid >> 1) * 32;     // warp col offset (o)

    const __nv_bfloat16* Ah = g_x1h + ((size_t)(b * NTOK + n0)) * NC;
    const __nv_bfloat16* Al = g_x1l + ((size_t)(b * NTOK + n0)) * NC;
    const __nv_bfloat16* Bh = g_W2h + ((size_t)(b * NO + o0)) * NC;
    const __nv_bfloat16* Bl = g_W2l + ((size_t)(b * NO + o0)) * NC;

    wmma::fragment<wmma::accumulator, 16, 16, 16, float> acc[4][2];
    #pragma unroll
    for (int i = 0; i < 4; i++)
        #pragma unroll
        for (int j = 0; j < 2; j++) wmma::fill_fragment(acc[i][j], 0.0f);

    for (int kt = 0; kt < NC / 32; ++kt) {
        const int koff = kt * 32;
        // load 4 tiles of [128 x 32] bf16; 512 uint4 per tile, 2 per thread
        #pragma unroll
        for (int s = 0; s < 2; s++) {
            const int idx = tid + s * 256;
            const int r = idx >> 2;
            const int c8 = (idx & 3) * 8;
            *(uint4*)(&sAh[r][c8]) = *(const uint4*)(Ah + (size_t)r * NC + koff + c8);
            *(uint4*)(&sAl[r][c8]) = *(const uint4*)(Al + (size_t)r * NC + koff + c8);
            *(uint4*)(&sBh[r][c8]) = *(const uint4*)(Bh + (size_t)r * NC + koff + c8);
            *(uint4*)(&sBl[r][c8]) = *(const uint4*)(Bl + (size_t)r * NC + koff + c8);
        }
        __syncthreads();
        #pragma unroll
        for (int kk = 0; kk < 2; kk++) {
            wmma::fragment<wmma::matrix_a, 16, 16, 16, __nv_bfloat16, wmma::row_major> ah[4], al[4];
            wmma::fragment<wmma::matrix_b, 16, 16, 16, __nv_bfloat16, wmma::col_major> bh[2], bl[2];
            #pragma unroll
            for (int i = 0; i < 4; i++) {
                wmma::load_matrix_sync(ah[i], &sAh[wn + i * 16][kk * 16], 32);
                wmma::load_matrix_sync(al[i], &sAl[wn + i * 16][kk * 16], 32);
            }
            #pragma unroll
            for (int j = 0; j < 2; j++) {
                wmma::load_matrix_sync(bh[j], &sBh[wo + j * 16][kk * 16], 32);
                wmma::load_matrix_sync(bl[j], &sBl[wo + j * 16][kk * 16], 32);
            }
            #pragma unroll
            for (int i = 0; i < 4; i++)
                #pragma unroll
                for (int j = 0; j < 2; j++) {
                    wmma::mma_sync(acc[i][j], ah[i], bh[j], acc[i][j]);
                    wmma::mma_sync(acc[i][j], ah[i], bl[j], acc[i][j]);
                    wmma::mma_sync(acc[i][j], al[i], bh[j], acc[i][j]);
                }
        }
        __syncthreads();
    }
    // epilogue: store straight to gmem (row-major, ld = NO)
    #pragma unroll
    for (int i = 0; i < 4; i++)
        #pragma unroll
        for (int j = 0; j < 2; j++) {
            float* dst = out + ((size_t)(b * NTOK + n0 + wn + i * 16)) * NO + o0 + wo + j * 16;
            wmma::store_matrix_sync(dst, acc[i][j], NO, wmma::mem_row_major);
        }
}

// ---------------- kernel 7: bias + LayerNorm over last dim (2048), in place ----------------
__global__ void ln_kernel(float* __restrict__ y,
                          const float* __restrict__ bias,
                          const float* __restrict__ gamma,
                          const float* __restrict__ beta) {
    const int bn = blockIdx.x;
    const int t = threadIdx.x;
    const int lane = t & 31, w = t >> 5;
    float4* row = (float4*)(y + (size_t)bn * NO);
    float4 v0 = row[t];
    float4 v1 = row[256 + t];
    const float4 bb0 = ((const float4*)bias)[t];
    const float4 bb1 = ((const float4*)bias)[256 + t];
    v0.x += bb0.x; v0.y += bb0.y; v0.z += bb0.z; v0.w += bb0.w;
    v1.x += bb1.x; v1.y += bb1.y; v1.z += bb1.z; v1.w += bb1.w;
    float s = v0.x + v0.y + v0.z + v0.w + v1.x + v1.y + v1.z + v1.w;
    #pragma unroll
    for (int off = 16; off; off >>= 1) s += __shfl_xor_sync(0xffffffffu, s, off);
    __shared__ float red1[8], red2[8];
    if (lane == 0) red1[w] = s;
    __syncthreads();
    float total = 0.f;
    #pragma unroll
    for (int i = 0; i < 8; i++) total += red1[i];
    const float mu = total * (1.0f / NO);
    float d, sq = 0.f;
    d = v0.x - mu; sq += d * d;  d = v0.y - mu; sq += d * d;
    d = v0.z - mu; sq += d * d;  d = v0.w - mu; sq += d * d;
    d = v1.x - mu; sq += d * d;  d = v1.y - mu; sq += d * d;
    d = v1.z - mu; sq += d * d;  d = v1.w - mu; sq += d * d;
    #pragma unroll
    for (int off = 16; off; off >>= 1) sq += __shfl_xor_sync(0xffffffffu, sq, off);
    if (lane == 0) red2[w] = sq;
    __syncthreads();
    float tot2 = 0.f;
    #pragma unroll
    for (int i = 0; i < 8; i++) tot2 += red2[i];
    const float rstd = rsqrtf(tot2 * (1.0f / NO) + 1e-5f);
    const float4 ga0 = ((const float4*)gamma)[t];
    const float4 ga1 = ((const float4*)gamma)[256 + t];
    const float4 be0 = ((const float4*)beta)[t];
    const float4 be1 = ((const float4*)beta)[256 + t];
    float4 o0, o1;
    o0.x = (v0.x - mu) * rstd * ga0.x + be0.x;
    o0.y = (v0.y - mu) * rstd * ga0.y + be0.y;
    o0.z = (v0.z - mu) * rstd * ga0.z + be0.z;
    o0.w = (v0.w - mu) * rstd * ga0.w + be0.w;
    o1.x = (v1.x - mu) * rstd * ga1.x + be1.x;
    o1.y = (v1.y - mu) * rstd * ga1.y + be1.y;
    o1.z = (v1.z - mu) * rstd * ga1.z + be1.z;
    o1.w = (v1.w - mu) * rstd * ga1.w + be1.w;
    row[t] = o0;
    row[256 + t] = o1;
}

// ---------------- launch ----------------
extern "C" void kernel_launch(void* const* d_in, const int* in_sizes, int n_in,
                              void* d_out, int out_size) {
    (void)in_sizes; (void)n_in; (void)out_size;
    const float* x1     = (const float*)d_in[0];
    const float* x2     = (const float*)d_in[1];
    const float* w_proj = (const float*)d_in[2];
    const float* b_proj = (const float*)d_in[3];
    const float* gamma  = (const float*)d_in[4];
    const float* beta   = (const float*)d_in[5];
    float* out = (float*)d_out;

    const int s_smem  = 128 * 132 * 4;          // 67584 B
    const int w2_smem = 2 * 128 * 132 * 4;      // 135168 B
    cudaFuncSetAttribute(s_kernel,  cudaFuncAttributeMaxDynamicSharedMemorySize, s_smem);
    cudaFuncSetAttribute(w2_kernel, cudaFuncAttributeMaxDynamicSharedMemorySize, w2_smem);

    qstats_kernel<<<NB * NTOK, 256>>>(x2);
    kstats_kernel<<<dim3(16, NB), 256>>>(x2);
    s_kernel<<<dim3(NCHUNK, NH, NB), 256, s_smem>>>(x2);
    s_reduce_kernel<<<NB * NH * HC, HC>>>();
    w2_kernel<<<dim3(16, NH, NB), 256, w2_smem>>>(w_proj);
    cvt_x1_kernel<<<(NB * NTOK * NC) / (256 * 4), 256>>>(x1);
    mm_kernel<<<dim3(NO / 128, NTOK / 128, NB), 256>>>(out);
    ln_kernel<<<NB * NTOK, 256>>>(out, b_proj, gamma, beta);
}

// round 15
// speedup vs baseline: 1.0843x; 1.0843x over previous
#include <cuda_runtime.h>
#include <cuda_bf16.h>
#include <mma.h>
#include <cstdint>
#include <math.h>

using namespace nvcuda;

// Problem constants
#define NB    4
#define NTOK  4096          // H*W
#define NC    1024          // C
#define NH    8             // heads
#define HC    128           // channels per head
#define NO    2048          // 2C
#define NCHUNK 32           // token chunks for S kernel (4096/128)

// ---------------- scratch (static device allocations only) ----------------
__device__ float g_qmax [NB * NTOK * NH];
__device__ float g_qfs  [NB * NTOK * NH];
__device__ float g_g    [NB * NC];
__device__ float g_Spart[(size_t)NB * NH * NCHUNK * HC * HC];   // 64 MB
__device__ float g_S    [NB * NH * HC * HC];                    // 2 MB
__device__ __nv_bfloat16 g_x1h[(size_t)NB * NTOK * NC];         // 32 MB
__device__ __nv_bfloat16 g_x1l[(size_t)NB * NTOK * NC];         // 32 MB
__device__ __nv_bfloat16 g_W2h[(size_t)NB * NO * NC];           // 16 MB
__device__ __nv_bfloat16 g_W2l[(size_t)NB * NO * NC];           // 16 MB

// packed f32x2 helpers (verified assembling in Round 10)
#define FMA_F32X2(acc, ap, bp) \
    asm("fma.rn.f32x2 %0, %1, %2, %0;" : "+l"(acc) : "l"(ap), "l"(bp))
#define BCAST_F32X2(out, f) \
    asm("mov.b64 %0, {%1, %1};" : "=l"(out) : "f"(f))
#define UNPACK_F32X2(lo, hi, in) \
    asm("mov.b64 {%0, %1}, %2;" : "=f"(lo), "=f"(hi) : "l"(in))

// cp.async helpers (sm_80 baseline PTX, no arch-suffix gating)
#define CP_ASYNC16(dst_smem_u32, src_gmem_ptr) \
    asm volatile("cp.async.cg.shared.global [%0], [%1], 16;" \
                 :: "r"(dst_smem_u32), "l"(src_gmem_ptr))
#define CP_COMMIT() asm volatile("cp.async.commit_group;" ::: "memory")
#define CP_WAIT1()  asm volatile("cp.async.wait_group 1;" ::: "memory")
#define CP_WAIT0()  asm volatile("cp.async.wait_group 0;" ::: "memory")

// ---------------- kernel 1: per-token (query) softmax stats ----------------
__global__ void qstats_kernel(const float* __restrict__ x2) {
    const int bn   = blockIdx.x;
    const int w    = threadIdx.x >> 5;
    const int lane = threadIdx.x & 31;
    const float4 v = *(const float4*)(x2 + (size_t)bn * NC + w * HC + lane * 4);
    float m = fmaxf(fmaxf(v.x, v.y), fmaxf(v.z, v.w));
    #pragma unroll
    for (int off = 16; off; off >>= 1) m = fmaxf(m, __shfl_xor_sync(0xffffffffu, m, off));
    float s = __expf(v.x - m) + __expf(v.y - m) + __expf(v.z - m) + __expf(v.w - m);
    #pragma unroll
    for (int off = 16; off; off >>= 1) s += __shfl_xor_sync(0xffffffffu, s, off);
    if (lane == 0) {
        g_qmax[bn * NH + w] = m;
        g_qfs [bn * NH + w] = sqrtf(__expf(m) / s);
    }
}

// ---------------- kernel 2: per-column (key) softmax stats ----------------
__global__ void kstats_kernel(const float* __restrict__ x2) {
    const int b   = blockIdx.y;
    const int ch0 = blockIdx.x * 64;
    const int t   = threadIdx.x;
    const int q   = t & 15;
    const int ro  = t >> 4;
    const float* base = x2 + (size_t)b * NTOK * NC + ch0 + q * 4;
    float m[4] = {-1e30f, -1e30f, -1e30f, -1e30f};
    float s[4] = {0.f, 0.f, 0.f, 0.f};
    for (int it = 0; it < NTOK / 16; ++it) {
        float4 v = *(const float4*)(base + (size_t)(it * 16 + ro) * NC);
        float vv[4] = {v.x, v.y, v.z, v.w};
        #pragma unroll
        for (int k = 0; k < 4; k++) {
            float x = vv[k];
            if (x > m[k]) { s[k] = s[k] * __expf(m[k] - x) + 1.0f; m[k] = x; }
            else          { s[k] += __expf(x - m[k]); }
        }
    }
    __shared__ float sm[16][64];
    __shared__ float ss[16][64];
    #pragma unroll
    for (int k = 0; k < 4; k++) { sm[ro][q * 4 + k] = m[k]; ss[ro][q * 4 + k] = s[k]; }
    __syncthreads();
    if (t < 64) {
        float M = -1e30f;
        #pragma unroll
        for (int r = 0; r < 16; r++) M = fmaxf(M, sm[r][t]);
        float S = 0.f;
        #pragma unroll
        for (int r = 0; r < 16; r++) S += ss[r][t] * __expf(sm[r][t] - M);
        g_g[b * NC + ch0 + t] = __expf(-M) / S;
    }
}

// ---------------- kernel 3: S partials (f32x2 FFMA2 inner loop) ----------------
__global__ void __launch_bounds__(256) s_kernel(const float* __restrict__ x2) {
    extern __shared__ float Es[];                 // [128][132]
    const int b = blockIdx.z, h = blockIdx.y, chunk = blockIdx.x;
    const int n0 = chunk * 128;
    const int t = threadIdx.x;
    {
        const int r  = t >> 1;
        const int c0 = (t & 1) * 64;
        const int n  = n0 + r;
        const float qm = g_qmax[(b * NTOK + n) * NH + h];
        const float qf = g_qfs [(b * NTOK + n) * NH + h];
        const float4* src = (const float4*)(x2 + (size_t)(b * NTOK + n) * NC + h * HC + c0);
        float* dst = Es + r * 132 + c0;
        #pragma unroll
        for (int k = 0; k < 16; k++) {
            float4 v = src[k];
            v.x = __expf(v.x - qm) * qf;
            v.y = __expf(v.y - qm) * qf;
            v.z = __expf(v.z - qm) * qf;
            v.w = __expf(v.w - qm) * qf;
            *(float4*)(dst + k * 4) = v;
        }
    }
    __syncthreads();
    const int tx = t & 15, ty = t >> 4;
    unsigned long long acc2[8][4];
    #pragma unroll
    for (int i = 0; i < 8; i++)
        #pragma unroll
        for (int j = 0; j < 4; j++) acc2[i][j] = 0ull;

    for (int n = 0; n < 128; n++) {
        const float* row = Es + n * 132;
        const float4 A0 = *(const float4*)(row + ty * 4);
        const float4 A1 = *(const float4*)(row + 64 + ty * 4);
        const ulonglong2 B0 = *(const ulonglong2*)(row + tx * 4);
        const ulonglong2 B1 = *(const ulonglong2*)(row + 64 + tx * 4);
        const unsigned long long bp[4] = {B0.x, B0.y, B1.x, B1.y};
        const float a[8] = {A0.x, A0.y, A0.z, A0.w, A1.x, A1.y, A1.z, A1.w};
        #pragma unroll
        for (int i = 0; i < 8; i++) {
            unsigned long long ap;
            BCAST_F32X2(ap, a[i]);
            #pragma unroll
            for (int j = 0; j < 4; j++) FMA_F32X2(acc2[i][j], ap, bp[j]);
        }
    }
    float gv[8];
    #pragma unroll
    for (int j = 0; j < 8; j++) {
        const int jg = (j < 4) ? (tx * 4 + j) : (64 + tx * 4 + (j - 4));
        gv[j] = g_g[b * NC + h * HC + jg];
    }
    float* Sout = g_Spart + (((size_t)(b * NH + h) * NCHUNK + chunk) * HC) * HC;
    #pragma unroll
    for (int i = 0; i < 8; i++) {
        float c[8];
        #pragma unroll
        for (int j = 0; j < 4; j++) UNPACK_F32X2(c[j * 2], c[j * 2 + 1], acc2[i][j]);
        const int ig = (i < 4) ? (ty * 4 + i) : (64 + ty * 4 + (i - 4));
        float* drow = Sout + ig * HC;
        *(float4*)(drow + tx * 4) =
            make_float4(c[0] * gv[0], c[1] * gv[1], c[2] * gv[2], c[3] * gv[3]);
        *(float4*)(drow + 64 + tx * 4) =
            make_float4(c[4] * gv[4], c[5] * gv[5], c[6] * gv[6], c[7] * gv[7]);
    }
}

// ---------------- kernel 4: reduce S partials ----------------
__global__ void s_reduce_kernel() {
    const int bh_i = blockIdx.x;
    const int j    = threadIdx.x;
    const int bh   = bh_i >> 7;
    const int i    = bh_i & 127;
    float s = 0.f;
    #pragma unroll 4
    for (int c = 0; c < NCHUNK; c++)
        s += g_Spart[(((size_t)bh * NCHUNK + c) * HC + i) * HC + j];
    g_S[((size_t)bh * HC + i) * HC + j] = s;
}

// ---------------- kernel 5: fold S into weights, emit bf16 hi/lo (f32x2 inner) ----------------
__global__ void __launch_bounds__(256) w2_kernel(const float* __restrict__ w_proj) {
    extern __shared__ float smemf[];
    float* Ssh = smemf;                    // [128][132]
    float* WT  = smemf + 128 * 132;        // [128][132]
    const int b = blockIdx.z, h = blockIdx.y, o0 = blockIdx.x * 128;
    const int t = threadIdx.x;
    {
        const int i = t >> 1, j0 = (t & 1) * 64;
        const float4* src = (const float4*)(g_S + ((size_t)(b * NH + h) * HC + i) * HC + j0);
        float4* dst = (float4*)(Ssh + i * 132 + j0);
        #pragma unroll
        for (int k = 0; k < 16; k++) dst[k] = src[k];
    }
    {
        const int o = t >> 1, i0 = (t & 1) * 64;
        const float4* src = (const float4*)(w_proj + (size_t)(o0 + o) * NC + h * HC + i0);
        #pragma unroll
        for (int k = 0; k < 16; k++) {
            float4 v = src[k];
            const int i = i0 + k * 4;
            WT[(i + 0) * 132 + o] = v.x;
            WT[(i + 1) * 132 + o] = v.y;
            WT[(i + 2) * 132 + o] = v.z;
            WT[(i + 3) * 132 + o] = v.w;
        }
    }
    __syncthreads();
    const int tx = t & 15, ty = t >> 4;
    unsigned long long acc2[8][4];
    #pragma unroll
    for (int i = 0; i < 8; i++)
        #pragma unroll
        for (int j = 0; j < 4; j++) acc2[i][j] = 0ull;

    for (int i = 0; i < 128; i++) {
        const float* wrow = WT  + i * 132;
        const float* srow = Ssh + i * 132;
        const float4 A0 = *(const float4*)(wrow + ty * 4);
        const float4 A1 = *(const float4*)(wrow + 64 + ty * 4);
        const ulonglong2 B0 = *(const ulonglong2*)(srow + tx * 4);
        const ulonglong2 B1 = *(const ulonglong2*)(srow + 64 + tx * 4);
        const unsigned long long bp[4] = {B0.x, B0.y, B1.x, B1.y};
        const float a[8] = {A0.x, A0.y, A0.z, A0.w, A1.x, A1.y, A1.z, A1.w};
        #pragma unroll
        for (int ii = 0; ii < 8; ii++) {
            unsigned long long ap;
            BCAST_F32X2(ap, a[ii]);
            #pragma unroll
            for (int jj = 0; jj < 4; jj++) FMA_F32X2(acc2[ii][jj], ap, bp[jj]);
        }
    }
    #pragma unroll
    for (int i = 0; i < 8; i++) {
        float c[8];
        #pragma unroll
        for (int j = 0; j < 4; j++) UNPACK_F32X2(c[j * 2], c[j * 2 + 1], acc2[i][j]);
        const int og = o0 + ((i < 4) ? (ty * 4 + i) : (64 + ty * 4 + (i - 4)));
        const size_t base = ((size_t)b * NO + og) * NC + h * HC;
        #pragma unroll
        for (int j = 0; j < 8; j++) {
            const int jg = (j < 4) ? (tx * 4 + j) : (64 + tx * 4 + (j - 4));
            float v = c[j];
            __nv_bfloat16 hi = __float2bfloat16_rn(v);
            __nv_bfloat16 lo = __float2bfloat16_rn(v - __bfloat162float(hi));
            g_W2h[base + jg] = hi;
            g_W2l[base + jg] = lo;
        }
    }
}

// ---------------- kernel 5b: x1 -> bf16 hi/lo ----------------
__global__ void cvt_x1_kernel(const float* __restrict__ x1) {
    const size_t i = ((size_t)blockIdx.x * 256 + threadIdx.x) * 4;
    const float4 v = *(const float4*)(x1 + i);
    float vv[4] = {v.x, v.y, v.z, v.w};
    __nv_bfloat16 h[4], l[4];
    #pragma unroll
    for (int k = 0; k < 4; k++) {
        h[k] = __float2bfloat16_rn(vv[k]);
        l[k] = __float2bfloat16_rn(vv[k] - __bfloat162float(h[k]));
    }
    ((__nv_bfloat162*)(g_x1h + i))[0] = __nv_bfloat162(h[0], h[1]);
    ((__nv_bfloat162*)(g_x1h + i))[1] = __nv_bfloat162(h[2], h[3]);
    ((__nv_bfloat162*)(g_x1l + i))[0] = __nv_bfloat162(l[0], l[1]);
    ((__nv_bfloat162*)(g_x1l + i))[1] = __nv_bfloat162(l[2], l[3]);
}

// ---------------- kernel 6: WMMA split-bf16 GEMM, cp.async double-buffered ----------------
// out[b, n0+r, o0+c] = sum_k x1[b,n0+r,k] * W2[b,o0+c,k]     (bias folded into LN)
// CTA tile 128x128, 8 warps 2(n) x 4(o); warp tile 64x32; K chunked by 32, 2-deep pipeline.
// Split products: hi*hi + hi*lo + lo*hi (lo*lo dropped, ~2^-16 rel).
// Dynamic smem: 2 buffers x 4 tiles x [128x32] bf16 = 65536 B.
#define MM_TILE_ELEMS 4096            // 128*32
__global__ void __launch_bounds__(256) mm_kernel(float* __restrict__ out) {
    extern __shared__ __nv_bfloat16 smbf[];
    __nv_bfloat16* SAh = smbf;                     // [2][4096]
    __nv_bfloat16* SAl = smbf + 2 * MM_TILE_ELEMS;
    __nv_bfloat16* SBh = smbf + 4 * MM_TILE_ELEMS;
    __nv_bfloat16* SBl = smbf + 6 * MM_TILE_ELEMS;

    const int b  = blockIdx.z;
    const int n0 = blockIdx.y * 128;
    const int o0 = blockIdx.x * 128;
    const int tid = threadIdx.x;
    const int wid = tid >> 5;
    const int wn = (wid & 1) * 64;      // warp row offset (n)
    const int wo = (wid >> 1) * 32;     // warp col offset (o)

    const __nv_bfloat16* Ah = g_x1h + ((size_t)(b * NTOK + n0)) * NC;
    const __nv_bfloat16* Al = g_x1l + ((size_t)(b * NTOK + n0)) * NC;
    const __nv_bfloat16* Bh = g_W2h + ((size_t)(b * NO + o0)) * NC;
    const __nv_bfloat16* Bl = g_W2l + ((size_t)(b * NO + o0)) * NC;

    // per-thread copy slice: 2 x 16B per tile
    const int r0  = tid >> 2;           // row for s=0
    const int c80 = (tid & 3) * 8;      // col (elements)
    auto issue = [&](int kt, int buf) {
        const int koff = kt * 32;
        #pragma unroll
        for (int s = 0; s < 2; s++) {
            const int r = r0 + s * 64;
            const size_t go = (size_t)r * NC + koff + c80;
            const int so = buf * MM_TILE_ELEMS + r * 32 + c80;
            CP_ASYNC16((uint32_t)__cvta_generic_to_shared(SAh + so), Ah + go);
            CP_ASYNC16((uint32_t)__cvta_generic_to_shared(SAl + so), Al + go);
            CP_ASYNC16((uint32_t)__cvta_generic_to_shared(SBh + so), Bh + go);
            CP_ASYNC16((uint32_t)__cvta_generic_to_shared(SBl + so), Bl + go);
        }
        CP_COMMIT();
    };

    wmma::fragment<wmma::accumulator, 16, 16, 16, float> acc[4][2];
    #pragma unroll
    for (int i = 0; i < 4; i++)
        #pragma unroll
        for (int j = 0; j < 2; j++) wmma::fill_fragment(acc[i][j], 0.0f);

    issue(0, 0);
    for (int kt = 0; kt < NC / 32; ++kt) {
        const int buf = kt & 1;
        if (kt + 1 < NC / 32) { issue(kt + 1, buf ^ 1); CP_WAIT1(); }
        else                  { CP_WAIT0(); }
        __syncthreads();

        const __nv_bfloat16* pAh = SAh + buf * MM_TILE_ELEMS;
        const __nv_bfloat16* pAl = SAl + buf * MM_TILE_ELEMS;
        const __nv_bfloat16* pBh = SBh + buf * MM_TILE_ELEMS;
        const __nv_bfloat16* pBl = SBl + buf * MM_TILE_ELEMS;
        #pragma unroll
        for (int kk = 0; kk < 2; kk++) {
            wmma::fragment<wmma::matrix_b, 16, 16, 16, __nv_bfloat16, wmma::col_major> bhf[2], blf[2];
            #pragma unroll
            for (int j = 0; j < 2; j++) {
                wmma::load_matrix_sync(bhf[j], pBh + (wo + j * 16) * 32 + kk * 16, 32);
                wmma::load_matrix_sync(blf[j], pBl + (wo + j * 16) * 32 + kk * 16, 32);
            }
            {   // hi-A products against both B halves (reuse af for hi then lo)
                wmma::fragment<wmma::matrix_a, 16, 16, 16, __nv_bfloat16, wmma::row_major> af[4];
                #pragma unroll
                for (int i = 0; i < 4; i++)
                    wmma::load_matrix_sync(af[i], pAh + (wn + i * 16) * 32 + kk * 16, 32);
                #pragma unroll
                for (int i = 0; i < 4; i++)
                    #pragma unroll
                    for (int j = 0; j < 2; j++) wmma::mma_sync(acc[i][j], af[i], bhf[j], acc[i][j]);
                #pragma unroll
                for (int i = 0; i < 4; i++)
                    #pragma unroll
                    for (int j = 0; j < 2; j++) wmma::mma_sync(acc[i][j], af[i], blf[j], acc[i][j]);
            }
            {   // lo-A against hi-B
                wmma::fragment<wmma::matrix_a, 16, 16, 16, __nv_bfloat16, wmma::row_major> af[4];
                #pragma unroll
                for (int i = 0; i < 4; i++)
                    wmma::load_matrix_sync(af[i], pAl + (wn + i * 16) * 32 + kk * 16, 32);
                #pragma unroll
                for (int i = 0; i < 4; i++)
                    #pragma unroll
                    for (int j = 0; j < 2; j++) wmma::mma_sync(acc[i][j], af[i], bhf[j], acc[i][j]);
            }
        }
        __syncthreads();
    }
    // epilogue: store straight to gmem (row-major, ld = NO)
    #pragma unroll
    for (int i = 0; i < 4; i++)
        #pragma unroll
        for (int j = 0; j < 2; j++) {
            float* dst = out + ((size_t)(b * NTOK + n0 + wn + i * 16)) * NO + o0 + wo + j * 16;
            wmma::store_matrix_sync(dst, acc[i][j], NO, wmma::mem_row_major);
        }
}

// ---------------- kernel 7: bias + LayerNorm over last dim (2048), in place ----------------
__global__ void ln_kernel(float* __restrict__ y,
                          const float* __restrict__ bias,
                          const float* __restrict__ gamma,
                          const float* __restrict__ beta) {
    const int bn = blockIdx.x;
    const int t = threadIdx.x;
    const int lane = t & 31, w = t >> 5;
    float4* row = (float4*)(y + (size_t)bn * NO);
    float4 v0 = row[t];
    float4 v1 = row[256 + t];
    const float4 bb0 = ((const float4*)bias)[t];
    const float4 bb1 = ((const float4*)bias)[256 + t];
    v0.x += bb0.x; v0.y += bb0.y; v0.z += bb0.z; v0.w += bb0.w;
    v1.x += bb1.x; v1.y += bb1.y; v1.z += bb1.z; v1.w += bb1.w;
    float s = v0.x + v0.y + v0.z + v0.w + v1.x + v1.y + v1.z + v1.w;
    #pragma unroll
    for (int off = 16; off; off >>= 1) s += __shfl_xor_sync(0xffffffffu, s, off);
    __shared__ float red1[8], red2[8];
    if (lane == 0) red1[w] = s;
    __syncthreads();
    float total = 0.f;
    #pragma unroll
    for (int i = 0; i < 8; i++) total += red1[i];
    const float mu = total * (1.0f / NO);
    float d, sq = 0.f;
    d = v0.x - mu; sq += d * d;  d = v0.y - mu; sq += d * d;
    d = v0.z - mu; sq += d * d;  d = v0.w - mu; sq += d * d;
    d = v1.x - mu; sq += d * d;  d = v1.y - mu; sq += d * d;
    d = v1.z - mu; sq += d * d;  d = v1.w - mu; sq += d * d;
    #pragma unroll
    for (int off = 16; off; off >>= 1) sq += __shfl_xor_sync(0xffffffffu, sq, off);
    if (lane == 0) red2[w] = sq;
    __syncthreads();
    float tot2 = 0.f;
    #pragma unroll
    for (int i = 0; i < 8; i++) tot2 += red2[i];
    const float rstd = rsqrtf(tot2 * (1.0f / NO) + 1e-5f);
    const float4 ga0 = ((const float4*)gamma)[t];
    const float4 ga1 = ((const float4*)gamma)[256 + t];
    const float4 be0 = ((const float4*)beta)[t];
    const float4 be1 = ((const float4*)beta)[256 + t];
    float4 o0, o1;
    o0.x = (v0.x - mu) * rstd * ga0.x + be0.x;
    o0.y = (v0.y - mu) * rstd * ga0.y + be0.y;
    o0.z = (v0.z - mu) * rstd * ga0.z + be0.z;
    o0.w = (v0.w - mu) * rstd * ga0.w + be0.w;
    o1.x = (v1.x - mu) * rstd * ga1.x + be1.x;
    o1.y = (v1.y - mu) * rstd * ga1.y + be1.y;
    o1.z = (v1.z - mu) * rstd * ga1.z + be1.z;
    o1.w = (v1.w - mu) * rstd * ga1.w + be1.w;
    row[t] = o0;
    row[256 + t] = o1;
}

// ---------------- launch ----------------
extern "C" void kernel_launch(void* const* d_in, const int* in_sizes, int n_in,
                              void* d_out, int out_size) {
    (void)in_sizes; (void)n_in; (void)out_size;
    const float* x1     = (const float*)d_in[0];
    const float* x2     = (const float*)d_in[1];
    const float* w_proj = (const float*)d_in[2];
    const float* b_proj = (const float*)d_in[3];
    const float* gamma  = (const float*)d_in[4];
    const float* beta   = (const float*)d_in[5];
    float* out = (float*)d_out;

    const int s_smem  = 128 * 132 * 4;          // 67584 B
    const int w2_smem = 2 * 128 * 132 * 4;      // 135168 B
    const int mm_smem = 8 * MM_TILE_ELEMS * 2;  // 65536 B
    cudaFuncSetAttribute(s_kernel,  cudaFuncAttributeMaxDynamicSharedMemorySize, s_smem);
    cudaFuncSetAttribute(w2_kernel, cudaFuncAttributeMaxDynamicSharedMemorySize, w2_smem);
    cudaFuncSetAttribute(mm_kernel, cudaFuncAttributeMaxDynamicSharedMemorySize, mm_smem);

    qstats_kernel<<<NB * NTOK, 256>>>(x2);
    kstats_kernel<<<dim3(16, NB), 256>>>(x2);
    s_kernel<<<dim3(NCHUNK, NH, NB), 256, s_smem>>>(x2);
    s_reduce_kernel<<<NB * NH * HC, HC>>>();
    w2_kernel<<<dim3(16, NH, NB), 256, w2_smem>>>(w_proj);
    cvt_x1_kernel<<<(NB * NTOK * NC) / (256 * 4), 256>>>(x1);
    mm_kernel<<<dim3(NO / 128, NTOK / 128, NB), 256, mm_smem>>>(out);
    ln_kernel<<<NB * NTOK, 256>>>(out, b_proj, gamma, beta);
}